// round 1
// baseline (speedup 1.0000x reference)
#include <cuda_runtime.h>
#include <cuda_bf16.h>

// ---------------------------------------------------------------------------
// EarthAttention3D  (Pangu-Weather window attention)
//   x:(15,64,144,192)  mask:(15,64,144,144)  qkv_w:(576,192) qkv_b:(576)
//   proj_w:(192,192)   proj_b:(192)          bias_table:(3312,64,6)
//   out:(15,64,144,192) fp32
// Pipeline:
//   K1 qkv GEMM  -> scatter to g_q (pre-scaled), g_k, g_v  [b_][w][h][n][l]
//   K2 bias pre-gather -> g_bias[h][w][n][m]
//   K3 fused attention per (b_,w,h): S=qk^T+bias+mask, softmax, O=PV -> g_o
//   K4 proj GEMM -> d_out
// ---------------------------------------------------------------------------

#define B_TOT   15
#define NW      64
#define NTOK    144
#define CCH     192
#define NH      6
#define LD      32
#define THREEC  576
#define MROWS   (B_TOT * NW * NTOK)          // 138240
#define NN      (NTOK * NTOK)                // 20736
#define QKV_PER_CTA (NTOK * LD)              // 4608
#define SCALE_Q 0.17677669529663687f         // 32^-0.5

// scratch (static __device__ arrays are the sanctioned workaround)
__device__ float g_q[B_TOT * NW * NH * NTOK * LD];   // 26.5M
__device__ float g_k[B_TOT * NW * NH * NTOK * LD];
__device__ float g_v[B_TOT * NW * NH * NTOK * LD];
__device__ float g_o[MROWS * CCH];                   // 26.5M
__device__ float g_bias[NH * NW * NTOK * NTOK];      // 7.96M

// ---------------------------------------------------------------------------
// K1: qkv = x @ qkv_w^T + qkv_b, scattered into g_q/g_k/g_v
// tile 128x64, K-chunk 16, 128 threads, 8x8 per thread
// ---------------------------------------------------------------------------
__global__ __launch_bounds__(128) void qkv_gemm_kernel(
    const float* __restrict__ x, const float* __restrict__ w,
    const float* __restrict__ bias)
{
    __shared__ float As[16][128 + 4];
    __shared__ float Bs[16][64 + 4];

    const int tid  = threadIdx.x;
    const int tx   = tid & 7;        // 8 col-groups of 8
    const int ty   = tid >> 3;       // 16 row-groups of 8
    const int row0 = blockIdx.y * 128;
    const int col0 = blockIdx.x * 64;

    float acc[8][8];
#pragma unroll
    for (int i = 0; i < 8; i++)
#pragma unroll
        for (int j = 0; j < 8; j++) acc[i][j] = 0.f;

    for (int k0 = 0; k0 < CCH; k0 += 16) {
        // A tile: 128 rows x 16 k = 512 float4
#pragma unroll
        for (int i = 0; i < 4; i++) {
            int f4 = tid + i * 128;
            int m = f4 >> 2, kq = f4 & 3;
            float4 v = *(const float4*)(x + (size_t)(row0 + m) * CCH + k0 + kq * 4);
            As[kq * 4 + 0][m] = v.x; As[kq * 4 + 1][m] = v.y;
            As[kq * 4 + 2][m] = v.z; As[kq * 4 + 3][m] = v.w;
        }
        // B tile: 64 rows(c) x 16 k = 256 float4 (B = w[c][k], i.e. w^T view)
#pragma unroll
        for (int i = 0; i < 2; i++) {
            int f4 = tid + i * 128;
            int c = f4 >> 2, kq = f4 & 3;
            float4 v = *(const float4*)(w + (size_t)(col0 + c) * CCH + k0 + kq * 4);
            Bs[kq * 4 + 0][c] = v.x; Bs[kq * 4 + 1][c] = v.y;
            Bs[kq * 4 + 2][c] = v.z; Bs[kq * 4 + 3][c] = v.w;
        }
        __syncthreads();
#pragma unroll
        for (int kk = 0; kk < 16; kk++) {
            float a[8], b[8];
#pragma unroll
            for (int i = 0; i < 8; i++) a[i] = As[kk][ty * 8 + i];
#pragma unroll
            for (int j = 0; j < 8; j++) b[j] = Bs[kk][tx * 8 + j];
#pragma unroll
            for (int i = 0; i < 8; i++)
#pragma unroll
                for (int j = 0; j < 8; j++) acc[i][j] += a[i] * b[j];
        }
        __syncthreads();
    }

    // epilogue scatter: c -> (part,h,l), r -> (b_,w_,n)
#pragma unroll
    for (int i = 0; i < 8; i++) {
        int r  = row0 + ty * 8 + i;
        int b_ = r / (NW * NTOK);
        int w_ = (r / NTOK) % NW;
        int n  = r % NTOK;
        size_t rb = ((size_t)(b_ * NW + w_) * NH);
#pragma unroll
        for (int j = 0; j < 8; j++) {
            int c    = col0 + tx * 8 + j;
            float v  = acc[i][j] + bias[c];
            int part = c / CCH;
            int hc   = c % CCH;
            int h    = hc >> 5;
            int l    = hc & 31;
            if (part == 0) v *= SCALE_Q;
            float* dst = (part == 0) ? g_q : (part == 1) ? g_k : g_v;
            dst[(((rb + h) * NTOK) + n) * LD + l] = v;
        }
    }
}

// ---------------------------------------------------------------------------
// K2: bias pre-gather  g_bias[h][w][n][m] = bias_table[epi(n,m)][w][h]
// ---------------------------------------------------------------------------
__global__ void bias_gather_kernel(const float* __restrict__ table)
{
    int idx = blockIdx.x * 256 + threadIdx.x;
    const int total = NH * NW * NTOK * NTOK;
    if (idx >= total) return;
    int m = idx % NTOK;
    int t = idx / NTOK;
    int n = t % NTOK;
    int t2 = t / NTOK;
    int w = t2 % NW;
    int h = t2 / NW;

    int zn = n / 72, latn = (n / 12) % 6, lonn = n % 12;
    int zm = m / 72, latm = (m / 12) % 6, lonm = m % 12;
    int epi = 828 * (zn + 2 * zm) + 23 * (latn + 6 * latm) + (lonn - lonm + 11);
    g_bias[idx] = table[(epi * NW + w) * NH + h];
}

// ---------------------------------------------------------------------------
// K3: fused attention. One CTA per (b_,w,h). 128 threads (4 warps x 36 rows).
// smem: sq[n][l], skT[l][m] (pad 148), svT[l][m] (pad 148), sp[warp][6][148]
// ---------------------------------------------------------------------------
__global__ __launch_bounds__(128) void attn_kernel(const float* __restrict__ mask)
{
    extern __shared__ float smem[];
    float* sq  = smem;                  // 4608
    float* skT = smem + 4608;           // 32*148 = 4736
    float* svT = skT + 4736;            // 4736
    float* sp  = svT + 4736;            // 4 * 6*148 = 3552

    const int cta = blockIdx.x;         // (b_*64+w)*6+h
    const int h   = cta % NH;
    const int bw  = cta / NH;           // b_*64+w
    const int w   = bw % NW;

    const float* gq = g_q + (size_t)cta * QKV_PER_CTA;
    const float* gk = g_k + (size_t)cta * QKV_PER_CTA;
    const float* gv = g_v + (size_t)cta * QKV_PER_CTA;

    const int tid = threadIdx.x;

    // load q (already scaled), coalesced float4
    for (int i = tid; i < QKV_PER_CTA / 4; i += 128)
        ((float4*)sq)[i] = ((const float4*)gq)[i];
    // k,v transposed into [l][m] with stride 148
    for (int i = tid; i < QKV_PER_CTA; i += 128) {
        int m = i >> 5, l = i & 31;
        skT[l * 148 + m] = gk[i];
        svT[l * 148 + m] = gv[i];
    }
    __syncthreads();

    const int wp   = tid >> 5;
    const int lane = tid & 31;
    const float* brow = g_bias + (size_t)(h * NW + w) * NN;
    const float* mrow = mask + (size_t)bw * NN;
    float* spw = sp + wp * (6 * 148);
    const int nbase = wp * 36;

    for (int g = 0; g < 6; g++) {
        const int n0 = nbase + g * 6;
        float acc[6][5];
#pragma unroll
        for (int r = 0; r < 6; r++)
#pragma unroll
            for (int j = 0; j < 5; j++) acc[r][j] = 0.f;

        const float* sqp = sq + n0 * LD;
#pragma unroll
        for (int l = 0; l < 32; l++) {
            float kv[5];
#pragma unroll
            for (int j = 0; j < 4; j++) kv[j] = skT[l * 148 + lane + 32 * j];
            kv[4] = (lane < 16) ? skT[l * 148 + lane + 128] : 0.f;
#pragma unroll
            for (int r = 0; r < 6; r++) {
                float qv = sqp[r * 32 + l];
#pragma unroll
                for (int j = 0; j < 5; j++) acc[r][j] += qv * kv[j];
            }
        }

        float invs[6];
#pragma unroll
        for (int r = 0; r < 6; r++) {
            const int n = n0 + r;
            float s[5];
            float mx = -3.0e38f;
#pragma unroll
            for (int j = 0; j < 5; j++) {
                int m = lane + 32 * j;
                float v = -3.0e38f;
                if (m < NTOK)
                    v = acc[r][j] + brow[n * NTOK + m] + mrow[n * NTOK + m];
                s[j] = v;
                mx = fmaxf(mx, v);
            }
#pragma unroll
            for (int off = 16; off; off >>= 1)
                mx = fmaxf(mx, __shfl_xor_sync(0xffffffffu, mx, off));
            float sum = 0.f;
#pragma unroll
            for (int j = 0; j < 5; j++) {
                float p = __expf(s[j] - mx);   // invalid lanes -> exp(-huge)=0
                s[j] = p;
                sum += p;
            }
#pragma unroll
            for (int off = 16; off; off >>= 1)
                sum += __shfl_xor_sync(0xffffffffu, sum, off);
            invs[r] = 1.f / sum;
#pragma unroll
            for (int j = 0; j < 5; j++) {
                int m = lane + 32 * j;
                if (m < NTOK) spw[r * 148 + m] = s[j];
            }
        }
        __syncwarp();

        // O = P V : lane owns column l=lane; svT[lane][m] = v[m][lane]
        float o[6] = {0.f, 0.f, 0.f, 0.f, 0.f, 0.f};
        const float4* v4p = (const float4*)(svT + lane * 148);
#pragma unroll
        for (int mq = 0; mq < 36; mq++) {
            float4 vv = v4p[mq];
#pragma unroll
            for (int r = 0; r < 6; r++) {
                float4 pp = ((const float4*)(spw + r * 148))[mq];
                o[r] += pp.x * vv.x + pp.y * vv.y + pp.z * vv.z + pp.w * vv.w;
            }
        }
#pragma unroll
        for (int r = 0; r < 6; r++)
            g_o[((size_t)bw * NTOK + n0 + r) * CCH + h * LD + lane] = o[r] * invs[r];
        __syncwarp();
    }
}

// ---------------------------------------------------------------------------
// K4: out = g_o @ proj_w^T + proj_b       (138240 x 192 x 192)
// ---------------------------------------------------------------------------
__global__ __launch_bounds__(128) void proj_gemm_kernel(
    const float* __restrict__ w, const float* __restrict__ bias,
    float* __restrict__ out)
{
    __shared__ float As[16][128 + 4];
    __shared__ float Bs[16][64 + 4];

    const int tid  = threadIdx.x;
    const int tx   = tid & 7;
    const int ty   = tid >> 3;
    const int row0 = blockIdx.y * 128;
    const int col0 = blockIdx.x * 64;

    float acc[8][8];
#pragma unroll
    for (int i = 0; i < 8; i++)
#pragma unroll
        for (int j = 0; j < 8; j++) acc[i][j] = 0.f;

    for (int k0 = 0; k0 < CCH; k0 += 16) {
#pragma unroll
        for (int i = 0; i < 4; i++) {
            int f4 = tid + i * 128;
            int m = f4 >> 2, kq = f4 & 3;
            float4 v = *(const float4*)(g_o + (size_t)(row0 + m) * CCH + k0 + kq * 4);
            As[kq * 4 + 0][m] = v.x; As[kq * 4 + 1][m] = v.y;
            As[kq * 4 + 2][m] = v.z; As[kq * 4 + 3][m] = v.w;
        }
#pragma unroll
        for (int i = 0; i < 2; i++) {
            int f4 = tid + i * 128;
            int c = f4 >> 2, kq = f4 & 3;
            float4 v = *(const float4*)(w + (size_t)(col0 + c) * CCH + k0 + kq * 4);
            Bs[kq * 4 + 0][c] = v.x; Bs[kq * 4 + 1][c] = v.y;
            Bs[kq * 4 + 2][c] = v.z; Bs[kq * 4 + 3][c] = v.w;
        }
        __syncthreads();
#pragma unroll
        for (int kk = 0; kk < 16; kk++) {
            float a[8], b[8];
#pragma unroll
            for (int i = 0; i < 8; i++) a[i] = As[kk][ty * 8 + i];
#pragma unroll
            for (int j = 0; j < 8; j++) b[j] = Bs[kk][tx * 8 + j];
#pragma unroll
            for (int i = 0; i < 8; i++)
#pragma unroll
                for (int j = 0; j < 8; j++) acc[i][j] += a[i] * b[j];
        }
        __syncthreads();
    }

#pragma unroll
    for (int i = 0; i < 8; i++) {
        int r = row0 + ty * 8 + i;
#pragma unroll
        for (int j = 0; j < 8; j++) {
            int c = col0 + tx * 8 + j;
            out[(size_t)r * CCH + c] = acc[i][j] + bias[c];
        }
    }
}

// ---------------------------------------------------------------------------
extern "C" void kernel_launch(void* const* d_in, const int* in_sizes, int n_in,
                              void* d_out, int out_size)
{
    (void)in_sizes; (void)n_in; (void)out_size;
    const float* x          = (const float*)d_in[0];
    const float* mask       = (const float*)d_in[1];
    const float* qkv_w      = (const float*)d_in[2];
    const float* qkv_b      = (const float*)d_in[3];
    const float* proj_w     = (const float*)d_in[4];
    const float* proj_b     = (const float*)d_in[5];
    const float* bias_table = (const float*)d_in[6];
    float* out = (float*)d_out;

    static const int ATTN_SMEM = (4608 + 4736 + 4736 + 3552) * 4;  // 70528 B
    cudaFuncSetAttribute(attn_kernel,
                         cudaFuncAttributeMaxDynamicSharedMemorySize, ATTN_SMEM);

    // K2 (independent of K1) then K1 -> K3 -> K4 on default stream
    {
        const int total = NH * NW * NTOK * NTOK;
        bias_gather_kernel<<<(total + 255) / 256, 256>>>(bias_table);
    }
    {
        dim3 grid(THREEC / 64, MROWS / 128);   // (9, 1080), n fast for L2 A-reuse
        qkv_gemm_kernel<<<grid, 128>>>(x, qkv_w, qkv_b);
    }
    attn_kernel<<<B_TOT * NW * NH, 128, ATTN_SMEM>>>(mask);
    {
        dim3 grid(CCH / 64, MROWS / 128);      // (3, 1080)
        proj_gemm_kernel<<<grid, 128>>>(proj_w, proj_b, out);
    }
}

// round 2
// speedup vs baseline: 1.3620x; 1.3620x over previous
#include <cuda_runtime.h>
#include <cuda_bf16.h>

// ---------------------------------------------------------------------------
// EarthAttention3D (Pangu-Weather window attention) — R2: tensor-core GEMMs
//   K1 qkv GEMM (bf16x3 mma.sync) -> scatter g_q (scaled), g_k, g_v
//   K2 bias pre-gather -> g_bias[h][w][n][m]
//   K3 fused attention per (b_,w,h)  (unchanged from R1)
//   K4 proj GEMM (bf16x3 mma.sync) -> d_out
// ---------------------------------------------------------------------------

#define B_TOT   15
#define NW      64
#define NTOK    144
#define CCH     192
#define NH      6
#define LD      32
#define THREEC  576
#define MROWS   (B_TOT * NW * NTOK)          // 138240
#define NN      (NTOK * NTOK)                // 20736
#define QKV_PER_CTA (NTOK * LD)              // 4608
#define SCALE_Q 0.17677669529663687f         // 32^-0.5

__device__ float g_q[B_TOT * NW * NH * NTOK * LD];
__device__ float g_k[B_TOT * NW * NH * NTOK * LD];
__device__ float g_v[B_TOT * NW * NH * NTOK * LD];
__device__ float g_o[MROWS * CCH];
__device__ float g_bias[NH * NW * NTOK * NTOK];

// ---------------------------------------------------------------------------
// bf16x3 split helpers: hi = truncate-to-bf16 (exact top 16 bits),
// lo = rn_bf16(x - hi).  Product hi*hi + lo*hi + hi*lo ~ fp32 (err ~2^-16).
// ---------------------------------------------------------------------------
__device__ __forceinline__ unsigned pack_hi(unsigned ux, unsigned uy) {
    // low half <- x's top 16 bits, high half <- y's top 16 bits
    return __byte_perm(ux, uy, 0x7632);
}
__device__ __forceinline__ unsigned pack_lo(float x, float y,
                                            unsigned ux, unsigned uy) {
    float rx = x - __uint_as_float(ux & 0xFFFF0000u);
    float ry = y - __uint_as_float(uy & 0xFFFF0000u);
    unsigned r;
    asm("cvt.rn.bf16x2.f32 %0, %1, %2;" : "=r"(r) : "f"(ry), "f"(rx));
    return r;
}
__device__ __forceinline__ void cvt_store(__nv_bfloat16* dh, __nv_bfloat16* dl,
                                          float4 v0, float4 v1) {
    unsigned u0 = __float_as_uint(v0.x), u1 = __float_as_uint(v0.y);
    unsigned u2 = __float_as_uint(v0.z), u3 = __float_as_uint(v0.w);
    unsigned u4 = __float_as_uint(v1.x), u5 = __float_as_uint(v1.y);
    unsigned u6 = __float_as_uint(v1.z), u7 = __float_as_uint(v1.w);
    uint4 hh, ll;
    hh.x = pack_hi(u0, u1); hh.y = pack_hi(u2, u3);
    hh.z = pack_hi(u4, u5); hh.w = pack_hi(u6, u7);
    ll.x = pack_lo(v0.x, v0.y, u0, u1); ll.y = pack_lo(v0.z, v0.w, u2, u3);
    ll.z = pack_lo(v1.x, v1.y, u4, u5); ll.w = pack_lo(v1.z, v1.w, u6, u7);
    *(uint4*)dh = hh;
    *(uint4*)dl = ll;
}

__device__ __forceinline__ void mma_bf16(float c[4], const unsigned a[4],
                                         const unsigned b[2]) {
    asm volatile(
        "mma.sync.aligned.m16n8k16.row.col.f32.bf16.bf16.f32 "
        "{%0,%1,%2,%3},{%4,%5,%6,%7},{%8,%9},{%0,%1,%2,%3};"
        : "+f"(c[0]), "+f"(c[1]), "+f"(c[2]), "+f"(c[3])
        : "r"(a[0]), "r"(a[1]), "r"(a[2]), "r"(a[3]), "r"(b[0]), "r"(b[1]));
}

// ---------------------------------------------------------------------------
// K1: qkv = x @ qkv_w^T + qkv_b via bf16x3 mma. CTA tile 128x64, 8 warps.
// ---------------------------------------------------------------------------
__global__ __launch_bounds__(256) void qkv_mma_kernel(
    const float* __restrict__ x, const float* __restrict__ w,
    const float* __restrict__ wb)
{
    __shared__ __nv_bfloat16 Ah[128][40];
    __shared__ __nv_bfloat16 Al[128][40];
    __shared__ __nv_bfloat16 Bh[64][40];
    __shared__ __nv_bfloat16 Bl[64][40];

    const int tid  = threadIdx.x;
    const int lane = tid & 31;
    const int warp = tid >> 5;
    const int wm = warp >> 1, wn = warp & 1;   // 4x2 warp grid, 32x32 tiles
    const int qr = lane >> 2, qc = lane & 3;
    const int row0 = blockIdx.y * 128, col0 = blockIdx.x * 64;

    float acc[2][4][4];
#pragma unroll
    for (int i = 0; i < 2; i++)
#pragma unroll
        for (int j = 0; j < 4; j++)
#pragma unroll
            for (int r = 0; r < 4; r++) acc[i][j][r] = 0.f;

    for (int c6 = 0; c6 < 6; c6++) {
        const int k0 = c6 * 32;
        // global prefetch (fp32)
        float4 av[2][2];
        int arow[2], akq[2];
#pragma unroll
        for (int i = 0; i < 2; i++) {
            int s = tid + i * 256;
            arow[i] = s >> 2; akq[i] = s & 3;
            const float4* p = (const float4*)(x + (size_t)(row0 + arow[i]) * CCH
                                              + k0 + akq[i] * 8);
            av[i][0] = p[0]; av[i][1] = p[1];
        }
        float4 bv[2];
        const int brow = tid >> 2, bkq = tid & 3;
        {
            const float4* p = (const float4*)(w + (size_t)(col0 + brow) * CCH
                                              + k0 + bkq * 8);
            bv[0] = p[0]; bv[1] = p[1];
        }
        __syncthreads();
#pragma unroll
        for (int i = 0; i < 2; i++)
            cvt_store(&Ah[arow[i]][akq[i] * 8], &Al[arow[i]][akq[i] * 8],
                      av[i][0], av[i][1]);
        cvt_store(&Bh[brow][bkq * 8], &Bl[brow][bkq * 8], bv[0], bv[1]);
        __syncthreads();

#pragma unroll
        for (int sub = 0; sub < 3; sub++) {
            const __nv_bfloat16 (*As)[40] = (sub == 1) ? Al : Ah;
            const __nv_bfloat16 (*Bs)[40] = (sub == 2) ? Bl : Bh;
#pragma unroll
            for (int kk = 0; kk < 2; kk++) {
                unsigned a[2][4];
#pragma unroll
                for (int mf = 0; mf < 2; mf++) {
                    const __nv_bfloat16* p = &As[wm * 32 + mf * 16 + qr][kk * 16 + qc * 2];
                    a[mf][0] = *(const unsigned*)p;
                    a[mf][1] = *(const unsigned*)(p + 8 * 40);
                    a[mf][2] = *(const unsigned*)(p + 8);
                    a[mf][3] = *(const unsigned*)(p + 8 * 40 + 8);
                }
#pragma unroll
                for (int nf = 0; nf < 4; nf++) {
                    unsigned b[2];
                    const __nv_bfloat16* p = &Bs[wn * 32 + nf * 8 + qr][kk * 16 + qc * 2];
                    b[0] = *(const unsigned*)p;
                    b[1] = *(const unsigned*)(p + 8);
                    mma_bf16(acc[0][nf], a[0], b);
                    mma_bf16(acc[1][nf], a[1], b);
                }
            }
        }
    }

    // epilogue: scatter c -> (part,h,l), r -> (b_,w_,n)
#pragma unroll
    for (int mf = 0; mf < 2; mf++) {
#pragma unroll
        for (int rr = 0; rr < 2; rr++) {
            int r  = row0 + wm * 32 + mf * 16 + qr + rr * 8;
            int b_ = r / (NW * NTOK);
            int w_ = (r / NTOK) % NW;
            int n  = r % NTOK;
            size_t rb = (size_t)(b_ * NW + w_) * NH;
#pragma unroll
            for (int nf = 0; nf < 4; nf++) {
#pragma unroll
                for (int cc = 0; cc < 2; cc++) {
                    int cg = col0 + wn * 32 + nf * 8 + qc * 2 + cc;
                    float v = acc[mf][nf][rr * 2 + cc] + wb[cg];
                    int part = cg / CCH;
                    int hc   = cg % CCH;
                    int h    = hc >> 5;
                    int l    = hc & 31;
                    if (part == 0) v *= SCALE_Q;
                    float* dst = (part == 0) ? g_q : (part == 1) ? g_k : g_v;
                    dst[((rb + h) * NTOK + n) * LD + l] = v;
                }
            }
        }
    }
}

// ---------------------------------------------------------------------------
// K4: out = g_o @ proj_w^T + proj_b via bf16x3 mma (same structure)
// ---------------------------------------------------------------------------
__global__ __launch_bounds__(256) void proj_mma_kernel(
    const float* __restrict__ w, const float* __restrict__ pb,
    float* __restrict__ out)
{
    __shared__ __nv_bfloat16 Ah[128][40];
    __shared__ __nv_bfloat16 Al[128][40];
    __shared__ __nv_bfloat16 Bh[64][40];
    __shared__ __nv_bfloat16 Bl[64][40];

    const int tid  = threadIdx.x;
    const int lane = tid & 31;
    const int warp = tid >> 5;
    const int wm = warp >> 1, wn = warp & 1;
    const int qr = lane >> 2, qc = lane & 3;
    const int row0 = blockIdx.y * 128, col0 = blockIdx.x * 64;

    float acc[2][4][4];
#pragma unroll
    for (int i = 0; i < 2; i++)
#pragma unroll
        for (int j = 0; j < 4; j++)
#pragma unroll
            for (int r = 0; r < 4; r++) acc[i][j][r] = 0.f;

    for (int c6 = 0; c6 < 6; c6++) {
        const int k0 = c6 * 32;
        float4 av[2][2];
        int arow[2], akq[2];
#pragma unroll
        for (int i = 0; i < 2; i++) {
            int s = tid + i * 256;
            arow[i] = s >> 2; akq[i] = s & 3;
            const float4* p = (const float4*)(g_o + (size_t)(row0 + arow[i]) * CCH
                                              + k0 + akq[i] * 8);
            av[i][0] = p[0]; av[i][1] = p[1];
        }
        float4 bv[2];
        const int brow = tid >> 2, bkq = tid & 3;
        {
            const float4* p = (const float4*)(w + (size_t)(col0 + brow) * CCH
                                              + k0 + bkq * 8);
            bv[0] = p[0]; bv[1] = p[1];
        }
        __syncthreads();
#pragma unroll
        for (int i = 0; i < 2; i++)
            cvt_store(&Ah[arow[i]][akq[i] * 8], &Al[arow[i]][akq[i] * 8],
                      av[i][0], av[i][1]);
        cvt_store(&Bh[brow][bkq * 8], &Bl[brow][bkq * 8], bv[0], bv[1]);
        __syncthreads();

#pragma unroll
        for (int sub = 0; sub < 3; sub++) {
            const __nv_bfloat16 (*As)[40] = (sub == 1) ? Al : Ah;
            const __nv_bfloat16 (*Bs)[40] = (sub == 2) ? Bl : Bh;
#pragma unroll
            for (int kk = 0; kk < 2; kk++) {
                unsigned a[2][4];
#pragma unroll
                for (int mf = 0; mf < 2; mf++) {
                    const __nv_bfloat16* p = &As[wm * 32 + mf * 16 + qr][kk * 16 + qc * 2];
                    a[mf][0] = *(const unsigned*)p;
                    a[mf][1] = *(const unsigned*)(p + 8 * 40);
                    a[mf][2] = *(const unsigned*)(p + 8);
                    a[mf][3] = *(const unsigned*)(p + 8 * 40 + 8);
                }
#pragma unroll
                for (int nf = 0; nf < 4; nf++) {
                    unsigned b[2];
                    const __nv_bfloat16* p = &Bs[wn * 32 + nf * 8 + qr][kk * 16 + qc * 2];
                    b[0] = *(const unsigned*)p;
                    b[1] = *(const unsigned*)(p + 8);
                    mma_bf16(acc[0][nf], a[0], b);
                    mma_bf16(acc[1][nf], a[1], b);
                }
            }
        }
    }

#pragma unroll
    for (int mf = 0; mf < 2; mf++) {
#pragma unroll
        for (int rr = 0; rr < 2; rr++) {
            int r = row0 + wm * 32 + mf * 16 + qr + rr * 8;
#pragma unroll
            for (int nf = 0; nf < 4; nf++) {
#pragma unroll
                for (int cc = 0; cc < 2; cc++) {
                    int cg = col0 + wn * 32 + nf * 8 + qc * 2 + cc;
                    out[(size_t)r * CCH + cg] = acc[mf][nf][rr * 2 + cc] + pb[cg];
                }
            }
        }
    }
}

// ---------------------------------------------------------------------------
// K2: bias pre-gather  g_bias[h][w][n][m] = bias_table[epi(n,m)][w][h]
// ---------------------------------------------------------------------------
__global__ void bias_gather_kernel(const float* __restrict__ table)
{
    int idx = blockIdx.x * 256 + threadIdx.x;
    const int total = NH * NW * NTOK * NTOK;
    if (idx >= total) return;
    int m = idx % NTOK;
    int t = idx / NTOK;
    int n = t % NTOK;
    int t2 = t / NTOK;
    int w = t2 % NW;
    int h = t2 / NW;

    int zn = n / 72, latn = (n / 12) % 6, lonn = n % 12;
    int zm = m / 72, latm = (m / 12) % 6, lonm = m % 12;
    int epi = 828 * (zn + 2 * zm) + 23 * (latn + 6 * latm) + (lonn - lonm + 11);
    g_bias[idx] = table[(epi * NW + w) * NH + h];
}

// ---------------------------------------------------------------------------
// K3: fused attention (unchanged from R1). One CTA per (b_,w,h). 128 threads.
// ---------------------------------------------------------------------------
__global__ __launch_bounds__(128) void attn_kernel(const float* __restrict__ mask)
{
    extern __shared__ float smem[];
    float* sq  = smem;                  // 4608
    float* skT = smem + 4608;           // 32*148
    float* svT = skT + 4736;            // 32*148
    float* sp  = svT + 4736;            // 4*6*148

    const int cta = blockIdx.x;         // (b_*64+w)*6+h
    const int h   = cta % NH;
    const int bw  = cta / NH;
    const int w   = bw % NW;

    const float* gq = g_q + (size_t)cta * QKV_PER_CTA;
    const float* gk = g_k + (size_t)cta * QKV_PER_CTA;
    const float* gv = g_v + (size_t)cta * QKV_PER_CTA;

    const int tid = threadIdx.x;

    for (int i = tid; i < QKV_PER_CTA / 4; i += 128)
        ((float4*)sq)[i] = ((const float4*)gq)[i];
    for (int i = tid; i < QKV_PER_CTA; i += 128) {
        int m = i >> 5, l = i & 31;
        skT[l * 148 + m] = gk[i];
        svT[l * 148 + m] = gv[i];
    }
    __syncthreads();

    const int wp   = tid >> 5;
    const int lane = tid & 31;
    const float* brow = g_bias + (size_t)(h * NW + w) * NN;
    const float* mrow = mask + (size_t)bw * NN;
    float* spw = sp + wp * (6 * 148);
    const int nbase = wp * 36;

    for (int g = 0; g < 6; g++) {
        const int n0 = nbase + g * 6;
        float acc[6][5];
#pragma unroll
        for (int r = 0; r < 6; r++)
#pragma unroll
            for (int j = 0; j < 5; j++) acc[r][j] = 0.f;

        const float* sqp = sq + n0 * LD;
#pragma unroll
        for (int l = 0; l < 32; l++) {
            float kv[5];
#pragma unroll
            for (int j = 0; j < 4; j++) kv[j] = skT[l * 148 + lane + 32 * j];
            kv[4] = (lane < 16) ? skT[l * 148 + lane + 128] : 0.f;
#pragma unroll
            for (int r = 0; r < 6; r++) {
                float qv = sqp[r * 32 + l];
#pragma unroll
                for (int j = 0; j < 5; j++) acc[r][j] += qv * kv[j];
            }
        }

        float invs[6];
#pragma unroll
        for (int r = 0; r < 6; r++) {
            const int n = n0 + r;
            float s[5];
            float mx = -3.0e38f;
#pragma unroll
            for (int j = 0; j < 5; j++) {
                int m = lane + 32 * j;
                float v = -3.0e38f;
                if (m < NTOK)
                    v = acc[r][j] + brow[n * NTOK + m] + mrow[n * NTOK + m];
                s[j] = v;
                mx = fmaxf(mx, v);
            }
#pragma unroll
            for (int off = 16; off; off >>= 1)
                mx = fmaxf(mx, __shfl_xor_sync(0xffffffffu, mx, off));
            float sum = 0.f;
#pragma unroll
            for (int j = 0; j < 5; j++) {
                float p = __expf(s[j] - mx);
                s[j] = p;
                sum += p;
            }
#pragma unroll
            for (int off = 16; off; off >>= 1)
                sum += __shfl_xor_sync(0xffffffffu, sum, off);
            invs[r] = 1.f / sum;
#pragma unroll
            for (int j = 0; j < 5; j++) {
                int m = lane + 32 * j;
                if (m < NTOK) spw[r * 148 + m] = s[j];
            }
        }
        __syncwarp();

        float o[6] = {0.f, 0.f, 0.f, 0.f, 0.f, 0.f};
        const float4* v4p = (const float4*)(svT + lane * 148);
#pragma unroll
        for (int mq = 0; mq < 36; mq++) {
            float4 vv = v4p[mq];
#pragma unroll
            for (int r = 0; r < 6; r++) {
                float4 pp = ((const float4*)(spw + r * 148))[mq];
                o[r] += pp.x * vv.x + pp.y * vv.y + pp.z * vv.z + pp.w * vv.w;
            }
        }
#pragma unroll
        for (int r = 0; r < 6; r++)
            g_o[((size_t)bw * NTOK + n0 + r) * CCH + h * LD + lane] = o[r] * invs[r];
        __syncwarp();
    }
}

// ---------------------------------------------------------------------------
extern "C" void kernel_launch(void* const* d_in, const int* in_sizes, int n_in,
                              void* d_out, int out_size)
{
    (void)in_sizes; (void)n_in; (void)out_size;
    const float* x          = (const float*)d_in[0];
    const float* mask       = (const float*)d_in[1];
    const float* qkv_w      = (const float*)d_in[2];
    const float* qkv_b      = (const float*)d_in[3];
    const float* proj_w     = (const float*)d_in[4];
    const float* proj_b     = (const float*)d_in[5];
    const float* bias_table = (const float*)d_in[6];
    float* out = (float*)d_out;

    static const int ATTN_SMEM = (4608 + 4736 + 4736 + 3552) * 4;  // 70528 B
    cudaFuncSetAttribute(attn_kernel,
                         cudaFuncAttributeMaxDynamicSharedMemorySize, ATTN_SMEM);

    {
        const int total = NH * NW * NTOK * NTOK;
        bias_gather_kernel<<<(total + 255) / 256, 256>>>(bias_table);
    }
    {
        dim3 grid(THREEC / 64, MROWS / 128);   // (9, 1080)
        qkv_mma_kernel<<<grid, 256>>>(x, qkv_w, qkv_b);
    }
    attn_kernel<<<B_TOT * NW * NH, 128, ATTN_SMEM>>>(mask);
    {
        dim3 grid(CCH / 64, MROWS / 128);      // (3, 1080)
        proj_mma_kernel<<<grid, 256>>>(proj_w, proj_b, out);
    }
}

// round 3
// speedup vs baseline: 1.8501x; 1.3584x over previous
#include <cuda_runtime.h>
#include <cuda_bf16.h>

// ---------------------------------------------------------------------------
// EarthAttention3D — R3: tensor-core attention (flash-style register P)
//   K1 qkv GEMM (bf16x3 mma) -> g_q (scaled), g_k, g_v
//   K2 bias pre-gather -> g_bias[h][w][n][m]
//   K3 attention: per (b_,w,h) CTA, 9 warps x 16 rows, S and PV via mma
//   K4 proj GEMM (bf16x3 mma) -> d_out
// ---------------------------------------------------------------------------

#define B_TOT   15
#define NW      64
#define NTOK    144
#define CCH     192
#define NH      6
#define LD      32
#define THREEC  576
#define MROWS   (B_TOT * NW * NTOK)          // 138240
#define NN      (NTOK * NTOK)                // 20736
#define QKV_PER_CTA (NTOK * LD)              // 4608
#define SCALE_Q 0.17677669529663687f         // 32^-0.5

__device__ float g_q[B_TOT * NW * NH * NTOK * LD];
__device__ float g_k[B_TOT * NW * NH * NTOK * LD];
__device__ float g_v[B_TOT * NW * NH * NTOK * LD];
__device__ float g_o[MROWS * CCH];
__device__ float g_bias[NH * NW * NTOK * NTOK];

// ---------------------------------------------------------------------------
// bf16x3 split helpers
// ---------------------------------------------------------------------------
__device__ __forceinline__ unsigned pack_hi(unsigned ux, unsigned uy) {
    return __byte_perm(ux, uy, 0x7632);      // lo16 <- hi16(x), hi16 <- hi16(y)
}
__device__ __forceinline__ unsigned pack_lo(float x, float y,
                                            unsigned ux, unsigned uy) {
    float rx = x - __uint_as_float(ux & 0xFFFF0000u);
    float ry = y - __uint_as_float(uy & 0xFFFF0000u);
    unsigned r;
    asm("cvt.rn.bf16x2.f32 %0, %1, %2;" : "=r"(r) : "f"(ry), "f"(rx));
    return r;
}
__device__ __forceinline__ void cvt_store(__nv_bfloat16* dh, __nv_bfloat16* dl,
                                          float4 v0, float4 v1) {
    unsigned u0 = __float_as_uint(v0.x), u1 = __float_as_uint(v0.y);
    unsigned u2 = __float_as_uint(v0.z), u3 = __float_as_uint(v0.w);
    unsigned u4 = __float_as_uint(v1.x), u5 = __float_as_uint(v1.y);
    unsigned u6 = __float_as_uint(v1.z), u7 = __float_as_uint(v1.w);
    uint4 hh, ll;
    hh.x = pack_hi(u0, u1); hh.y = pack_hi(u2, u3);
    hh.z = pack_hi(u4, u5); hh.w = pack_hi(u6, u7);
    ll.x = pack_lo(v0.x, v0.y, u0, u1); ll.y = pack_lo(v0.z, v0.w, u2, u3);
    ll.z = pack_lo(v1.x, v1.y, u4, u5); ll.w = pack_lo(v1.z, v1.w, u6, u7);
    *(uint4*)dh = hh;
    *(uint4*)dl = ll;
}

__device__ __forceinline__ void mma_bf16(float c[4], const unsigned a[4],
                                         const unsigned b[2]) {
    asm volatile(
        "mma.sync.aligned.m16n8k16.row.col.f32.bf16.bf16.f32 "
        "{%0,%1,%2,%3},{%4,%5,%6,%7},{%8,%9},{%0,%1,%2,%3};"
        : "+f"(c[0]), "+f"(c[1]), "+f"(c[2]), "+f"(c[3])
        : "r"(a[0]), "r"(a[1]), "r"(a[2]), "r"(a[3]), "r"(b[0]), "r"(b[1]));
}

// ---------------------------------------------------------------------------
// K1: qkv = x @ qkv_w^T + qkv_b via bf16x3 mma. CTA tile 128x64, 8 warps.
// ---------------------------------------------------------------------------
__global__ __launch_bounds__(256) void qkv_mma_kernel(
    const float* __restrict__ x, const float* __restrict__ w,
    const float* __restrict__ wb)
{
    __shared__ __nv_bfloat16 Ah[128][40];
    __shared__ __nv_bfloat16 Al[128][40];
    __shared__ __nv_bfloat16 Bh[64][40];
    __shared__ __nv_bfloat16 Bl[64][40];

    const int tid  = threadIdx.x;
    const int lane = tid & 31;
    const int warp = tid >> 5;
    const int wm = warp >> 1, wn = warp & 1;
    const int qr = lane >> 2, qc = lane & 3;
    const int row0 = blockIdx.y * 128, col0 = blockIdx.x * 64;

    float acc[2][4][4];
#pragma unroll
    for (int i = 0; i < 2; i++)
#pragma unroll
        for (int j = 0; j < 4; j++)
#pragma unroll
            for (int r = 0; r < 4; r++) acc[i][j][r] = 0.f;

    for (int c6 = 0; c6 < 6; c6++) {
        const int k0 = c6 * 32;
        float4 av[2][2];
        int arow[2], akq[2];
#pragma unroll
        for (int i = 0; i < 2; i++) {
            int s = tid + i * 256;
            arow[i] = s >> 2; akq[i] = s & 3;
            const float4* p = (const float4*)(x + (size_t)(row0 + arow[i]) * CCH
                                              + k0 + akq[i] * 8);
            av[i][0] = p[0]; av[i][1] = p[1];
        }
        float4 bv[2];
        const int brow = tid >> 2, bkq = tid & 3;
        {
            const float4* p = (const float4*)(w + (size_t)(col0 + brow) * CCH
                                              + k0 + bkq * 8);
            bv[0] = p[0]; bv[1] = p[1];
        }
        __syncthreads();
#pragma unroll
        for (int i = 0; i < 2; i++)
            cvt_store(&Ah[arow[i]][akq[i] * 8], &Al[arow[i]][akq[i] * 8],
                      av[i][0], av[i][1]);
        cvt_store(&Bh[brow][bkq * 8], &Bl[brow][bkq * 8], bv[0], bv[1]);
        __syncthreads();

#pragma unroll
        for (int sub = 0; sub < 3; sub++) {
            const __nv_bfloat16 (*As)[40] = (sub == 1) ? Al : Ah;
            const __nv_bfloat16 (*Bs)[40] = (sub == 2) ? Bl : Bh;
#pragma unroll
            for (int kk = 0; kk < 2; kk++) {
                unsigned a[2][4];
#pragma unroll
                for (int mf = 0; mf < 2; mf++) {
                    const __nv_bfloat16* p = &As[wm * 32 + mf * 16 + qr][kk * 16 + qc * 2];
                    a[mf][0] = *(const unsigned*)p;
                    a[mf][1] = *(const unsigned*)(p + 8 * 40);
                    a[mf][2] = *(const unsigned*)(p + 8);
                    a[mf][3] = *(const unsigned*)(p + 8 * 40 + 8);
                }
#pragma unroll
                for (int nf = 0; nf < 4; nf++) {
                    unsigned b[2];
                    const __nv_bfloat16* p = &Bs[wn * 32 + nf * 8 + qr][kk * 16 + qc * 2];
                    b[0] = *(const unsigned*)p;
                    b[1] = *(const unsigned*)(p + 8);
                    mma_bf16(acc[0][nf], a[0], b);
                    mma_bf16(acc[1][nf], a[1], b);
                }
            }
        }
    }

#pragma unroll
    for (int mf = 0; mf < 2; mf++) {
#pragma unroll
        for (int rr = 0; rr < 2; rr++) {
            int r  = row0 + wm * 32 + mf * 16 + qr + rr * 8;
            int b_ = r / (NW * NTOK);
            int w_ = (r / NTOK) % NW;
            int n  = r % NTOK;
            size_t rb = (size_t)(b_ * NW + w_) * NH;
#pragma unroll
            for (int nf = 0; nf < 4; nf++) {
#pragma unroll
                for (int cc = 0; cc < 2; cc++) {
                    int cg = col0 + wn * 32 + nf * 8 + qc * 2 + cc;
                    float v = acc[mf][nf][rr * 2 + cc] + wb[cg];
                    int part = cg / CCH;
                    int hc   = cg % CCH;
                    int h    = hc >> 5;
                    int l    = hc & 31;
                    if (part == 0) v *= SCALE_Q;
                    float* dst = (part == 0) ? g_q : (part == 1) ? g_k : g_v;
                    dst[((rb + h) * NTOK + n) * LD + l] = v;
                }
            }
        }
    }
}

// ---------------------------------------------------------------------------
// K4: out = g_o @ proj_w^T + proj_b via bf16x3 mma
// ---------------------------------------------------------------------------
__global__ __launch_bounds__(256) void proj_mma_kernel(
    const float* __restrict__ w, const float* __restrict__ pb,
    float* __restrict__ out)
{
    __shared__ __nv_bfloat16 Ah[128][40];
    __shared__ __nv_bfloat16 Al[128][40];
    __shared__ __nv_bfloat16 Bh[64][40];
    __shared__ __nv_bfloat16 Bl[64][40];

    const int tid  = threadIdx.x;
    const int lane = tid & 31;
    const int warp = tid >> 5;
    const int wm = warp >> 1, wn = warp & 1;
    const int qr = lane >> 2, qc = lane & 3;
    const int row0 = blockIdx.y * 128, col0 = blockIdx.x * 64;

    float acc[2][4][4];
#pragma unroll
    for (int i = 0; i < 2; i++)
#pragma unroll
        for (int j = 0; j < 4; j++)
#pragma unroll
            for (int r = 0; r < 4; r++) acc[i][j][r] = 0.f;

    for (int c6 = 0; c6 < 6; c6++) {
        const int k0 = c6 * 32;
        float4 av[2][2];
        int arow[2], akq[2];
#pragma unroll
        for (int i = 0; i < 2; i++) {
            int s = tid + i * 256;
            arow[i] = s >> 2; akq[i] = s & 3;
            const float4* p = (const float4*)(g_o + (size_t)(row0 + arow[i]) * CCH
                                              + k0 + akq[i] * 8);
            av[i][0] = p[0]; av[i][1] = p[1];
        }
        float4 bv[2];
        const int brow = tid >> 2, bkq = tid & 3;
        {
            const float4* p = (const float4*)(w + (size_t)(col0 + brow) * CCH
                                              + k0 + bkq * 8);
            bv[0] = p[0]; bv[1] = p[1];
        }
        __syncthreads();
#pragma unroll
        for (int i = 0; i < 2; i++)
            cvt_store(&Ah[arow[i]][akq[i] * 8], &Al[arow[i]][akq[i] * 8],
                      av[i][0], av[i][1]);
        cvt_store(&Bh[brow][bkq * 8], &Bl[brow][bkq * 8], bv[0], bv[1]);
        __syncthreads();

#pragma unroll
        for (int sub = 0; sub < 3; sub++) {
            const __nv_bfloat16 (*As)[40] = (sub == 1) ? Al : Ah;
            const __nv_bfloat16 (*Bs)[40] = (sub == 2) ? Bl : Bh;
#pragma unroll
            for (int kk = 0; kk < 2; kk++) {
                unsigned a[2][4];
#pragma unroll
                for (int mf = 0; mf < 2; mf++) {
                    const __nv_bfloat16* p = &As[wm * 32 + mf * 16 + qr][kk * 16 + qc * 2];
                    a[mf][0] = *(const unsigned*)p;
                    a[mf][1] = *(const unsigned*)(p + 8 * 40);
                    a[mf][2] = *(const unsigned*)(p + 8);
                    a[mf][3] = *(const unsigned*)(p + 8 * 40 + 8);
                }
#pragma unroll
                for (int nf = 0; nf < 4; nf++) {
                    unsigned b[2];
                    const __nv_bfloat16* p = &Bs[wn * 32 + nf * 8 + qr][kk * 16 + qc * 2];
                    b[0] = *(const unsigned*)p;
                    b[1] = *(const unsigned*)(p + 8);
                    mma_bf16(acc[0][nf], a[0], b);
                    mma_bf16(acc[1][nf], a[1], b);
                }
            }
        }
    }

#pragma unroll
    for (int mf = 0; mf < 2; mf++) {
#pragma unroll
        for (int rr = 0; rr < 2; rr++) {
            int r = row0 + wm * 32 + mf * 16 + qr + rr * 8;
#pragma unroll
            for (int nf = 0; nf < 4; nf++) {
#pragma unroll
                for (int cc = 0; cc < 2; cc++) {
                    int cg = col0 + wn * 32 + nf * 8 + qc * 2 + cc;
                    out[(size_t)r * CCH + cg] = acc[mf][nf][rr * 2 + cc] + pb[cg];
                }
            }
        }
    }
}

// ---------------------------------------------------------------------------
// K2: bias pre-gather
// ---------------------------------------------------------------------------
__global__ void bias_gather_kernel(const float* __restrict__ table)
{
    int idx = blockIdx.x * 256 + threadIdx.x;
    const int total = NH * NW * NTOK * NTOK;
    if (idx >= total) return;
    int m = idx % NTOK;
    int t = idx / NTOK;
    int n = t % NTOK;
    int t2 = t / NTOK;
    int w = t2 % NW;
    int h = t2 / NW;

    int zn = n / 72, latn = (n / 12) % 6, lonn = n % 12;
    int zm = m / 72, latm = (m / 12) % 6, lonm = m % 12;
    int epi = 828 * (zn + 2 * zm) + 23 * (latn + 6 * latm) + (lonn - lonm + 11);
    g_bias[idx] = table[(epi * NW + w) * NH + h];
}

// ---------------------------------------------------------------------------
// K3: tensor-core attention. CTA=(b_,w,h), 288 thr = 9 warps x 16 rows.
// smem (bf16): qh[144][40] ql kh kl | vTh[32][152] vTl   = 65536 B
// S acc (16x144) in regs; bias+mask add; quad-shuffle softmax;
// P stays in regs (S-accum layout == A-fragment layout); PV 3-pass split.
// ---------------------------------------------------------------------------
__global__ __launch_bounds__(288) void attn_mma_kernel(const float* __restrict__ mask)
{
    extern __shared__ __nv_bfloat16 sm[];
    __nv_bfloat16* qh  = sm;              // 144*40
    __nv_bfloat16* ql  = sm + 5760;
    __nv_bfloat16* kh  = sm + 11520;
    __nv_bfloat16* kl  = sm + 17280;
    __nv_bfloat16* vTh = sm + 23040;      // 32*152
    __nv_bfloat16* vTl = sm + 27904;

    const int cta = blockIdx.x;           // (b_*64+w)*6+h
    const int h   = cta % NH;
    const int bw  = cta / NH;
    const int w   = bw % NW;
    const int tid = threadIdx.x;

    const float* gq = g_q + (size_t)cta * QKV_PER_CTA;
    const float* gk = g_k + (size_t)cta * QKV_PER_CTA;
    const float* gv = g_v + (size_t)cta * QKV_PER_CTA;

    // q,k -> hi/lo smem (row stride 40)
    for (int c = tid; c < 576; c += 288) {
        int n = c >> 2, l0 = (c & 3) * 8;
        const float4* p = (const float4*)(gq + n * LD + l0);
        cvt_store(qh + n * 40 + l0, ql + n * 40 + l0, p[0], p[1]);
        const float4* pk = (const float4*)(gk + n * LD + l0);
        cvt_store(kh + n * 40 + l0, kl + n * 40 + l0, pk[0], pk[1]);
    }
    // v transposed -> vT[l][m] hi/lo (row stride 152)
    for (int c = tid; c < 1152; c += 288) {
        int m = c >> 3, l0 = (c & 7) * 4;
        float4 v = *(const float4*)(gv + m * LD + l0);
        float vals[4] = {v.x, v.y, v.z, v.w};
#pragma unroll
        for (int j = 0; j < 4; j++) {
            unsigned u = __float_as_uint(vals[j]);
            unsigned short hs = (unsigned short)(u >> 16);
            vTh[(l0 + j) * 152 + m] = *reinterpret_cast<__nv_bfloat16*>(&hs);
            float hif = __uint_as_float(u & 0xFFFF0000u);
            vTl[(l0 + j) * 152 + m] = __float2bfloat16(vals[j] - hif);
        }
    }
    __syncthreads();

    const int warp = tid >> 5;            // 0..8
    const int lane = tid & 31;
    const int qr = lane >> 2, qc = lane & 3;
    const int row0 = warp * 16;

    // ---- S = q k^T (bf16x3), 16x144 per warp ----
    float acc[18][4];
#pragma unroll
    for (int j = 0; j < 18; j++)
#pragma unroll
        for (int r = 0; r < 4; r++) acc[j][r] = 0.f;

#pragma unroll
    for (int sub = 0; sub < 3; sub++) {
        const __nv_bfloat16* Aq = (sub == 1) ? ql : qh;
        const __nv_bfloat16* Bk = (sub == 2) ? kl : kh;
#pragma unroll
        for (int kk = 0; kk < 2; kk++) {
            unsigned a[4];
            const __nv_bfloat16* pa = Aq + (row0 + qr) * 40 + kk * 16 + qc * 2;
            a[0] = *(const unsigned*)pa;
            a[1] = *(const unsigned*)(pa + 8 * 40);
            a[2] = *(const unsigned*)(pa + 8);
            a[3] = *(const unsigned*)(pa + 8 * 40 + 8);
#pragma unroll
            for (int j = 0; j < 18; j++) {
                unsigned b[2];
                const __nv_bfloat16* pb = Bk + (j * 8 + qr) * 40 + kk * 16 + qc * 2;
                b[0] = *(const unsigned*)pb;
                b[1] = *(const unsigned*)(pb + 8);
                mma_bf16(acc[j], a, b);
            }
        }
    }

    // ---- bias + mask, rowwise max ----
    const int r0g = row0 + qr, r1g = r0g + 8;
    const float* b0p = g_bias + ((size_t)(h * NW + w)) * NN + (size_t)r0g * NTOK;
    const float* b1p = b0p + 8 * NTOK;
    const float* m0p = mask + (size_t)bw * NN + (size_t)r0g * NTOK;
    const float* m1p = m0p + 8 * NTOK;

    float mx0 = -3.0e38f, mx1 = -3.0e38f;
#pragma unroll
    for (int j = 0; j < 18; j++) {
        int cb = j * 8 + qc * 2;
        float2 bb0 = *(const float2*)(b0p + cb);
        float2 mm0 = *(const float2*)(m0p + cb);
        acc[j][0] += bb0.x + mm0.x;
        acc[j][1] += bb0.y + mm0.y;
        float2 bb1 = *(const float2*)(b1p + cb);
        float2 mm1 = *(const float2*)(m1p + cb);
        acc[j][2] += bb1.x + mm1.x;
        acc[j][3] += bb1.y + mm1.y;
        mx0 = fmaxf(mx0, fmaxf(acc[j][0], acc[j][1]));
        mx1 = fmaxf(mx1, fmaxf(acc[j][2], acc[j][3]));
    }
    mx0 = fmaxf(mx0, __shfl_xor_sync(0xffffffffu, mx0, 1));
    mx0 = fmaxf(mx0, __shfl_xor_sync(0xffffffffu, mx0, 2));
    mx1 = fmaxf(mx1, __shfl_xor_sync(0xffffffffu, mx1, 1));
    mx1 = fmaxf(mx1, __shfl_xor_sync(0xffffffffu, mx1, 2));

    float s0 = 0.f, s1 = 0.f;
#pragma unroll
    for (int j = 0; j < 18; j++) {
        acc[j][0] = __expf(acc[j][0] - mx0);
        acc[j][1] = __expf(acc[j][1] - mx0);
        acc[j][2] = __expf(acc[j][2] - mx1);
        acc[j][3] = __expf(acc[j][3] - mx1);
        s0 += acc[j][0] + acc[j][1];
        s1 += acc[j][2] + acc[j][3];
    }
    s0 += __shfl_xor_sync(0xffffffffu, s0, 1);
    s0 += __shfl_xor_sync(0xffffffffu, s0, 2);
    s1 += __shfl_xor_sync(0xffffffffu, s1, 1);
    s1 += __shfl_xor_sync(0xffffffffu, s1, 2);
    const float inv0 = 1.f / s0, inv1 = 1.f / s1;

    // ---- O = P V (bf16x3): P fragments built from S accums in regs ----
    float o[4][4];
#pragma unroll
    for (int nf = 0; nf < 4; nf++)
#pragma unroll
        for (int r = 0; r < 4; r++) o[nf][r] = 0.f;

#pragma unroll
    for (int kt = 0; kt < 9; kt++) {
        const int t0 = 2 * kt, t1 = 2 * kt + 1;
        unsigned ah[4], al[4];
        {
            unsigned u0 = __float_as_uint(acc[t0][0]), u1 = __float_as_uint(acc[t0][1]);
            ah[0] = pack_hi(u0, u1);
            al[0] = pack_lo(acc[t0][0], acc[t0][1], u0, u1);
            unsigned u2 = __float_as_uint(acc[t0][2]), u3 = __float_as_uint(acc[t0][3]);
            ah[1] = pack_hi(u2, u3);
            al[1] = pack_lo(acc[t0][2], acc[t0][3], u2, u3);
            unsigned u4 = __float_as_uint(acc[t1][0]), u5 = __float_as_uint(acc[t1][1]);
            ah[2] = pack_hi(u4, u5);
            al[2] = pack_lo(acc[t1][0], acc[t1][1], u4, u5);
            unsigned u6 = __float_as_uint(acc[t1][2]), u7 = __float_as_uint(acc[t1][3]);
            ah[3] = pack_hi(u6, u7);
            al[3] = pack_lo(acc[t1][2], acc[t1][3], u6, u7);
        }
#pragma unroll
        for (int nf = 0; nf < 4; nf++) {
            unsigned bh[2], bl[2];
            const __nv_bfloat16* pbh = vTh + (nf * 8 + qr) * 152 + kt * 16 + qc * 2;
            const __nv_bfloat16* pbl = vTl + (nf * 8 + qr) * 152 + kt * 16 + qc * 2;
            bh[0] = *(const unsigned*)pbh; bh[1] = *(const unsigned*)(pbh + 8);
            bl[0] = *(const unsigned*)pbl; bl[1] = *(const unsigned*)(pbl + 8);
            mma_bf16(o[nf], ah, bh);
            mma_bf16(o[nf], al, bh);
            mma_bf16(o[nf], ah, bl);
        }
    }

    // ---- write O (normalized) to g_o ----
    float* o0 = g_o + ((size_t)(bw * NTOK + r0g)) * CCH + h * LD;
    float* o1 = g_o + ((size_t)(bw * NTOK + r1g)) * CCH + h * LD;
#pragma unroll
    for (int nf = 0; nf < 4; nf++) {
        int col = nf * 8 + qc * 2;
        float2 w0 = {o[nf][0] * inv0, o[nf][1] * inv0};
        float2 w1 = {o[nf][2] * inv1, o[nf][3] * inv1};
        *(float2*)(o0 + col) = w0;
        *(float2*)(o1 + col) = w1;
    }
}

// ---------------------------------------------------------------------------
extern "C" void kernel_launch(void* const* d_in, const int* in_sizes, int n_in,
                              void* d_out, int out_size)
{
    (void)in_sizes; (void)n_in; (void)out_size;
    const float* x          = (const float*)d_in[0];
    const float* mask       = (const float*)d_in[1];
    const float* qkv_w      = (const float*)d_in[2];
    const float* qkv_b      = (const float*)d_in[3];
    const float* proj_w     = (const float*)d_in[4];
    const float* proj_b     = (const float*)d_in[5];
    const float* bias_table = (const float*)d_in[6];
    float* out = (float*)d_out;

    static const int ATTN_SMEM = 65536;
    cudaFuncSetAttribute(attn_mma_kernel,
                         cudaFuncAttributeMaxDynamicSharedMemorySize, ATTN_SMEM);

    {
        const int total = NH * NW * NTOK * NTOK;
        bias_gather_kernel<<<(total + 255) / 256, 256>>>(bias_table);
    }
    {
        dim3 grid(THREEC / 64, MROWS / 128);   // (9, 1080)
        qkv_mma_kernel<<<grid, 256>>>(x, qkv_w, qkv_b);
    }
    attn_mma_kernel<<<B_TOT * NW * NH, 288, ATTN_SMEM>>>(mask);
    {
        dim3 grid(CCH / 64, MROWS / 128);      // (3, 1080)
        proj_mma_kernel<<<grid, 256>>>(proj_w, proj_b, out);
    }
}

// round 4
// speedup vs baseline: 1.8819x; 1.0172x over previous
#include <cuda_runtime.h>
#include <cuda_bf16.h>

// ---------------------------------------------------------------------------
// EarthAttention3D — R4: ldmatrix fragments + fragment-shared bf16x3 +
// double-buffered GEMMs.
// ---------------------------------------------------------------------------

#define B_TOT   15
#define NW      64
#define NTOK    144
#define CCH     192
#define NH      6
#define LD      32
#define THREEC  576
#define MROWS   (B_TOT * NW * NTOK)          // 138240
#define NN      (NTOK * NTOK)                // 20736
#define QKV_PER_CTA (NTOK * LD)              // 4608
#define SCALE_Q 0.17677669529663687f         // 32^-0.5

__device__ float g_q[B_TOT * NW * NH * NTOK * LD];
__device__ float g_k[B_TOT * NW * NH * NTOK * LD];
__device__ float g_v[B_TOT * NW * NH * NTOK * LD];
__device__ float g_o[MROWS * CCH];
__device__ float g_bias[NH * NW * NTOK * NTOK];

// ---------------------------------------------------------------------------
// helpers
// ---------------------------------------------------------------------------
__device__ __forceinline__ unsigned pack_hi(unsigned ux, unsigned uy) {
    return __byte_perm(ux, uy, 0x7632);
}
__device__ __forceinline__ unsigned pack_lo(float x, float y,
                                            unsigned ux, unsigned uy) {
    float rx = x - __uint_as_float(ux & 0xFFFF0000u);
    float ry = y - __uint_as_float(uy & 0xFFFF0000u);
    unsigned r;
    asm("cvt.rn.bf16x2.f32 %0, %1, %2;" : "=r"(r) : "f"(ry), "f"(rx));
    return r;
}
__device__ __forceinline__ void cvt_store(__nv_bfloat16* dh, __nv_bfloat16* dl,
                                          float4 v0, float4 v1) {
    unsigned u0 = __float_as_uint(v0.x), u1 = __float_as_uint(v0.y);
    unsigned u2 = __float_as_uint(v0.z), u3 = __float_as_uint(v0.w);
    unsigned u4 = __float_as_uint(v1.x), u5 = __float_as_uint(v1.y);
    unsigned u6 = __float_as_uint(v1.z), u7 = __float_as_uint(v1.w);
    uint4 hh, ll;
    hh.x = pack_hi(u0, u1); hh.y = pack_hi(u2, u3);
    hh.z = pack_hi(u4, u5); hh.w = pack_hi(u6, u7);
    ll.x = pack_lo(v0.x, v0.y, u0, u1); ll.y = pack_lo(v0.z, v0.w, u2, u3);
    ll.z = pack_lo(v1.x, v1.y, u4, u5); ll.w = pack_lo(v1.z, v1.w, u6, u7);
    *(uint4*)dh = hh;
    *(uint4*)dl = ll;
}
__device__ __forceinline__ void mma_bf16(float c[4], const unsigned a[4],
                                         const unsigned b[2]) {
    asm volatile(
        "mma.sync.aligned.m16n8k16.row.col.f32.bf16.bf16.f32 "
        "{%0,%1,%2,%3},{%4,%5,%6,%7},{%8,%9},{%0,%1,%2,%3};"
        : "+f"(c[0]), "+f"(c[1]), "+f"(c[2]), "+f"(c[3])
        : "r"(a[0]), "r"(a[1]), "r"(a[2]), "r"(a[3]), "r"(b[0]), "r"(b[1]));
}
__device__ __forceinline__ void ldsm_x4(unsigned r[4], unsigned addr) {
    asm volatile("ldmatrix.sync.aligned.m8n8.x4.shared.b16 {%0,%1,%2,%3}, [%4];"
                 : "=r"(r[0]), "=r"(r[1]), "=r"(r[2]), "=r"(r[3]) : "r"(addr));
}

// ---------------------------------------------------------------------------
// K1: qkv GEMM. CTA 128x64, 8 warps, double-buffered smem, ldmatrix frags.
// smem stage (bf16 units): Ah 0 (128x40), Al 5120, Bh 10240 (64x40), Bl 12800.
// stage stride 15360 bf16; total 61440 B.
// ---------------------------------------------------------------------------
__global__ __launch_bounds__(256, 2) void qkv_mma_kernel(
    const float* __restrict__ x, const float* __restrict__ w,
    const float* __restrict__ wb)
{
    extern __shared__ __nv_bfloat16 smg[];
    const unsigned sbase = (unsigned)__cvta_generic_to_shared(smg);

    const int tid  = threadIdx.x;
    const int lane = tid & 31;
    const int warp = tid >> 5;
    const int wm = warp >> 1, wn = warp & 1;
    const int qr = lane >> 2, qc = lane & 3;
    const int row0 = blockIdx.y * 128, col0 = blockIdx.x * 64;
    const int a_ro = (lane & 7) + ((lane & 8) ? 8 : 0);
    const int a_co = (lane & 16) ? 8 : 0;
    const int b_ro = (lane & 7) + ((lane & 16) ? 8 : 0);
    const int b_co = (lane & 8) ? 8 : 0;
    const int arow0 = tid >> 2, akq = tid & 3;

    float acc[2][4][4];
#pragma unroll
    for (int i = 0; i < 2; i++)
#pragma unroll
        for (int j = 0; j < 4; j++)
#pragma unroll
            for (int r = 0; r < 4; r++) acc[i][j][r] = 0.f;

    float4 av[2][2], bv[2];

    auto load_chunk = [&](int c) {
        const int k0 = c * 32;
#pragma unroll
        for (int i = 0; i < 2; i++) {
            const float4* p = (const float4*)(x + (size_t)(row0 + arow0 + 64 * i) * CCH
                                              + k0 + akq * 8);
            av[i][0] = p[0]; av[i][1] = p[1];
        }
        const float4* pB = (const float4*)(w + (size_t)(col0 + arow0 % 64) * CCH
                                           + k0 + akq * 8);
        bv[0] = pB[0]; bv[1] = pB[1];
    };
    auto store_chunk = [&](int s) {
        __nv_bfloat16* base = smg + s * 15360;
#pragma unroll
        for (int i = 0; i < 2; i++) {
            int ar = arow0 + 64 * i;
            cvt_store(base + ar * 40 + akq * 8, base + 5120 + ar * 40 + akq * 8,
                      av[i][0], av[i][1]);
        }
        int br = arow0 % 64;
        cvt_store(base + 10240 + br * 40 + akq * 8, base + 12800 + br * 40 + akq * 8,
                  bv[0], bv[1]);
    };
    auto mma_stage = [&](int s) {
        const unsigned stg = sbase + s * 15360 * 2;
#pragma unroll
        for (int kk = 0; kk < 2; kk++) {
            unsigned ah[2][4], al[2][4];
#pragma unroll
            for (int mf = 0; mf < 2; mf++) {
                unsigned off = ((wm * 32 + mf * 16 + a_ro) * 40 + kk * 16 + a_co) * 2;
                ldsm_x4(ah[mf], stg + off);
                ldsm_x4(al[mf], stg + 5120 * 2 + off);
            }
            unsigned bh[2][4], bl[2][4];
#pragma unroll
            for (int np = 0; np < 2; np++) {
                unsigned off = ((wn * 32 + np * 16 + b_ro) * 40 + kk * 16 + b_co) * 2;
                ldsm_x4(bh[np], stg + 10240 * 2 + off);
                ldsm_x4(bl[np], stg + 12800 * 2 + off);
            }
#pragma unroll
            for (int mf = 0; mf < 2; mf++)
#pragma unroll
                for (int np = 0; np < 2; np++) {
                    mma_bf16(acc[mf][np * 2],     ah[mf], &bh[np][0]);
                    mma_bf16(acc[mf][np * 2 + 1], ah[mf], &bh[np][2]);
                    mma_bf16(acc[mf][np * 2],     al[mf], &bh[np][0]);
                    mma_bf16(acc[mf][np * 2 + 1], al[mf], &bh[np][2]);
                    mma_bf16(acc[mf][np * 2],     ah[mf], &bl[np][0]);
                    mma_bf16(acc[mf][np * 2 + 1], ah[mf], &bl[np][2]);
                }
        }
    };

    load_chunk(0);
    store_chunk(0);
    __syncthreads();
#pragma unroll
    for (int c = 0; c < 6; c++) {
        if (c < 5) load_chunk(c + 1);
        mma_stage(c & 1);
        if (c < 5) { store_chunk((c + 1) & 1); __syncthreads(); }
    }

#pragma unroll
    for (int mf = 0; mf < 2; mf++) {
#pragma unroll
        for (int rr = 0; rr < 2; rr++) {
            int r  = row0 + wm * 32 + mf * 16 + qr + rr * 8;
            int b_ = r / (NW * NTOK);
            int w_ = (r / NTOK) % NW;
            int n  = r % NTOK;
            size_t rb = (size_t)(b_ * NW + w_) * NH;
#pragma unroll
            for (int nf = 0; nf < 4; nf++) {
#pragma unroll
                for (int cc = 0; cc < 2; cc++) {
                    int cg = col0 + wn * 32 + nf * 8 + qc * 2 + cc;
                    float v = acc[mf][nf][rr * 2 + cc] + wb[cg];
                    int part = cg / CCH;
                    int hc   = cg % CCH;
                    int h    = hc >> 5;
                    int l    = hc & 31;
                    if (part == 0) v *= SCALE_Q;
                    float* dst = (part == 0) ? g_q : (part == 1) ? g_k : g_v;
                    dst[((rb + h) * NTOK + n) * LD + l] = v;
                }
            }
        }
    }
}

// ---------------------------------------------------------------------------
// K4: proj GEMM (same engine, A = g_o, plain epilogue)
// ---------------------------------------------------------------------------
__global__ __launch_bounds__(256, 2) void proj_mma_kernel(
    const float* __restrict__ w, const float* __restrict__ pb,
    float* __restrict__ out)
{
    extern __shared__ __nv_bfloat16 smg[];
    const unsigned sbase = (unsigned)__cvta_generic_to_shared(smg);

    const int tid  = threadIdx.x;
    const int lane = tid & 31;
    const int warp = tid >> 5;
    const int wm = warp >> 1, wn = warp & 1;
    const int qr = lane >> 2, qc = lane & 3;
    const int row0 = blockIdx.y * 128, col0 = blockIdx.x * 64;
    const int a_ro = (lane & 7) + ((lane & 8) ? 8 : 0);
    const int a_co = (lane & 16) ? 8 : 0;
    const int b_ro = (lane & 7) + ((lane & 16) ? 8 : 0);
    const int b_co = (lane & 8) ? 8 : 0;
    const int arow0 = tid >> 2, akq = tid & 3;

    float acc[2][4][4];
#pragma unroll
    for (int i = 0; i < 2; i++)
#pragma unroll
        for (int j = 0; j < 4; j++)
#pragma unroll
            for (int r = 0; r < 4; r++) acc[i][j][r] = 0.f;

    float4 av[2][2], bv[2];

    auto load_chunk = [&](int c) {
        const int k0 = c * 32;
#pragma unroll
        for (int i = 0; i < 2; i++) {
            const float4* p = (const float4*)(g_o + (size_t)(row0 + arow0 + 64 * i) * CCH
                                              + k0 + akq * 8);
            av[i][0] = p[0]; av[i][1] = p[1];
        }
        const float4* pB = (const float4*)(w + (size_t)(col0 + arow0 % 64) * CCH
                                           + k0 + akq * 8);
        bv[0] = pB[0]; bv[1] = pB[1];
    };
    auto store_chunk = [&](int s) {
        __nv_bfloat16* base = smg + s * 15360;
#pragma unroll
        for (int i = 0; i < 2; i++) {
            int ar = arow0 + 64 * i;
            cvt_store(base + ar * 40 + akq * 8, base + 5120 + ar * 40 + akq * 8,
                      av[i][0], av[i][1]);
        }
        int br = arow0 % 64;
        cvt_store(base + 10240 + br * 40 + akq * 8, base + 12800 + br * 40 + akq * 8,
                  bv[0], bv[1]);
    };
    auto mma_stage = [&](int s) {
        const unsigned stg = sbase + s * 15360 * 2;
#pragma unroll
        for (int kk = 0; kk < 2; kk++) {
            unsigned ah[2][4], al[2][4];
#pragma unroll
            for (int mf = 0; mf < 2; mf++) {
                unsigned off = ((wm * 32 + mf * 16 + a_ro) * 40 + kk * 16 + a_co) * 2;
                ldsm_x4(ah[mf], stg + off);
                ldsm_x4(al[mf], stg + 5120 * 2 + off);
            }
            unsigned bh[2][4], bl[2][4];
#pragma unroll
            for (int np = 0; np < 2; np++) {
                unsigned off = ((wn * 32 + np * 16 + b_ro) * 40 + kk * 16 + b_co) * 2;
                ldsm_x4(bh[np], stg + 10240 * 2 + off);
                ldsm_x4(bl[np], stg + 12800 * 2 + off);
            }
#pragma unroll
            for (int mf = 0; mf < 2; mf++)
#pragma unroll
                for (int np = 0; np < 2; np++) {
                    mma_bf16(acc[mf][np * 2],     ah[mf], &bh[np][0]);
                    mma_bf16(acc[mf][np * 2 + 1], ah[mf], &bh[np][2]);
                    mma_bf16(acc[mf][np * 2],     al[mf], &bh[np][0]);
                    mma_bf16(acc[mf][np * 2 + 1], al[mf], &bh[np][2]);
                    mma_bf16(acc[mf][np * 2],     ah[mf], &bl[np][0]);
                    mma_bf16(acc[mf][np * 2 + 1], ah[mf], &bl[np][2]);
                }
        }
    };

    load_chunk(0);
    store_chunk(0);
    __syncthreads();
#pragma unroll
    for (int c = 0; c < 6; c++) {
        if (c < 5) load_chunk(c + 1);
        mma_stage(c & 1);
        if (c < 5) { store_chunk((c + 1) & 1); __syncthreads(); }
    }

#pragma unroll
    for (int mf = 0; mf < 2; mf++) {
#pragma unroll
        for (int rr = 0; rr < 2; rr++) {
            int r = row0 + wm * 32 + mf * 16 + qr + rr * 8;
#pragma unroll
            for (int nf = 0; nf < 4; nf++) {
#pragma unroll
                for (int cc = 0; cc < 2; cc++) {
                    int cg = col0 + wn * 32 + nf * 8 + qc * 2 + cc;
                    out[(size_t)r * CCH + cg] = acc[mf][nf][rr * 2 + cc] + pb[cg];
                }
            }
        }
    }
}

// ---------------------------------------------------------------------------
// K2: bias pre-gather
// ---------------------------------------------------------------------------
__global__ void bias_gather_kernel(const float* __restrict__ table)
{
    int idx = blockIdx.x * 256 + threadIdx.x;
    const int total = NH * NW * NTOK * NTOK;
    if (idx >= total) return;
    int m = idx % NTOK;
    int t = idx / NTOK;
    int n = t % NTOK;
    int t2 = t / NTOK;
    int w = t2 % NW;
    int h = t2 / NW;

    int zn = n / 72, latn = (n / 12) % 6, lonn = n % 12;
    int zm = m / 72, latm = (m / 12) % 6, lonm = m % 12;
    int epi = 828 * (zn + 2 * zm) + 23 * (latn + 6 * latm) + (lonn - lonm + 11);
    g_bias[idx] = table[(epi * NW + w) * NH + h];
}

// ---------------------------------------------------------------------------
// K3: tensor-core attention, ldmatrix + fragment-shared bf16x3.
// CTA=(b_,w,h), 288 thr = 9 warps x 16 rows.
// smem bf16: qh 0, ql 5760, kh 11520, kl 17280 (144x40 each),
//            vTh 23040, vTl 27904 (32x152 each) = 65536 B
// ---------------------------------------------------------------------------
__global__ __launch_bounds__(288) void attn_mma_kernel(const float* __restrict__ mask)
{
    extern __shared__ __nv_bfloat16 sm[];
    __nv_bfloat16* qh  = sm;
    __nv_bfloat16* ql  = sm + 5760;
    __nv_bfloat16* kh  = sm + 11520;
    __nv_bfloat16* kl  = sm + 17280;
    __nv_bfloat16* vTh = sm + 23040;
    __nv_bfloat16* vTl = sm + 27904;
    const unsigned sbase = (unsigned)__cvta_generic_to_shared(sm);

    const int cta = blockIdx.x;           // (b_*64+w)*6+h
    const int h   = cta % NH;
    const int bw  = cta / NH;
    const int w   = bw % NW;
    const int tid = threadIdx.x;

    const float* gq = g_q + (size_t)cta * QKV_PER_CTA;
    const float* gk = g_k + (size_t)cta * QKV_PER_CTA;
    const float* gv = g_v + (size_t)cta * QKV_PER_CTA;

    for (int c = tid; c < 576; c += 288) {
        int n = c >> 2, l0 = (c & 3) * 8;
        const float4* p = (const float4*)(gq + n * LD + l0);
        cvt_store(qh + n * 40 + l0, ql + n * 40 + l0, p[0], p[1]);
        const float4* pk = (const float4*)(gk + n * LD + l0);
        cvt_store(kh + n * 40 + l0, kl + n * 40 + l0, pk[0], pk[1]);
    }
    for (int c = tid; c < 1152; c += 288) {
        int m = c >> 3, l0 = (c & 7) * 4;
        float4 v = *(const float4*)(gv + m * LD + l0);
        float vals[4] = {v.x, v.y, v.z, v.w};
#pragma unroll
        for (int j = 0; j < 4; j++) {
            unsigned u = __float_as_uint(vals[j]);
            unsigned short hs = (unsigned short)(u >> 16);
            vTh[(l0 + j) * 152 + m] = *reinterpret_cast<__nv_bfloat16*>(&hs);
            float hif = __uint_as_float(u & 0xFFFF0000u);
            vTl[(l0 + j) * 152 + m] = __float2bfloat16(vals[j] - hif);
        }
    }
    __syncthreads();

    const int warp = tid >> 5;            // 0..8
    const int lane = tid & 31;
    const int qr = lane >> 2, qc = lane & 3;
    const int row0 = warp * 16;
    const int a_ro = (lane & 7) + ((lane & 8) ? 8 : 0);
    const int a_co = (lane & 16) ? 8 : 0;
    const int b_ro = (lane & 7) + ((lane & 16) ? 8 : 0);
    const int b_co = (lane & 8) ? 8 : 0;

    // ---- S = q k^T ----
    float acc[18][4];
#pragma unroll
    for (int j = 0; j < 18; j++)
#pragma unroll
        for (int r = 0; r < 4; r++) acc[j][r] = 0.f;

#pragma unroll
    for (int kk = 0; kk < 2; kk++) {
        unsigned qfh[4], qfl[4];
        {
            unsigned off = ((row0 + a_ro) * 40 + kk * 16 + a_co) * 2;
            ldsm_x4(qfh, sbase + off);                 // qh at 0
            ldsm_x4(qfl, sbase + 5760 * 2 + off);      // ql
        }
#pragma unroll
        for (int jt = 0; jt < 9; jt++) {
            unsigned kfh[4], kfl[4];
            unsigned off = ((jt * 16 + b_ro) * 40 + kk * 16 + b_co) * 2;
            ldsm_x4(kfh, sbase + 11520 * 2 + off);
            ldsm_x4(kfl, sbase + 17280 * 2 + off);
            mma_bf16(acc[2 * jt],     qfh, &kfh[0]);
            mma_bf16(acc[2 * jt + 1], qfh, &kfh[2]);
            mma_bf16(acc[2 * jt],     qfl, &kfh[0]);
            mma_bf16(acc[2 * jt + 1], qfl, &kfh[2]);
            mma_bf16(acc[2 * jt],     qfh, &kfl[0]);
            mma_bf16(acc[2 * jt + 1], qfh, &kfl[2]);
        }
    }

    // ---- bias + mask, rowwise softmax ----
    const int r0g = row0 + qr, r1g = r0g + 8;
    const float* b0p = g_bias + ((size_t)(h * NW + w)) * NN + (size_t)r0g * NTOK;
    const float* b1p = b0p + 8 * NTOK;
    const float* m0p = mask + (size_t)bw * NN + (size_t)r0g * NTOK;
    const float* m1p = m0p + 8 * NTOK;

    float mx0 = -3.0e38f, mx1 = -3.0e38f;
#pragma unroll
    for (int j = 0; j < 18; j++) {
        int cb = j * 8 + qc * 2;
        float2 bb0 = *(const float2*)(b0p + cb);
        float2 mm0 = *(const float2*)(m0p + cb);
        acc[j][0] += bb0.x + mm0.x;
        acc[j][1] += bb0.y + mm0.y;
        float2 bb1 = *(const float2*)(b1p + cb);
        float2 mm1 = *(const float2*)(m1p + cb);
        acc[j][2] += bb1.x + mm1.x;
        acc[j][3] += bb1.y + mm1.y;
        mx0 = fmaxf(mx0, fmaxf(acc[j][0], acc[j][1]));
        mx1 = fmaxf(mx1, fmaxf(acc[j][2], acc[j][3]));
    }
    mx0 = fmaxf(mx0, __shfl_xor_sync(0xffffffffu, mx0, 1));
    mx0 = fmaxf(mx0, __shfl_xor_sync(0xffffffffu, mx0, 2));
    mx1 = fmaxf(mx1, __shfl_xor_sync(0xffffffffu, mx1, 1));
    mx1 = fmaxf(mx1, __shfl_xor_sync(0xffffffffu, mx1, 2));

    float s0 = 0.f, s1 = 0.f;
#pragma unroll
    for (int j = 0; j < 18; j++) {
        acc[j][0] = __expf(acc[j][0] - mx0);
        acc[j][1] = __expf(acc[j][1] - mx0);
        acc[j][2] = __expf(acc[j][2] - mx1);
        acc[j][3] = __expf(acc[j][3] - mx1);
        s0 += acc[j][0] + acc[j][1];
        s1 += acc[j][2] + acc[j][3];
    }
    s0 += __shfl_xor_sync(0xffffffffu, s0, 1);
    s0 += __shfl_xor_sync(0xffffffffu, s0, 2);
    s1 += __shfl_xor_sync(0xffffffffu, s1, 1);
    s1 += __shfl_xor_sync(0xffffffffu, s1, 2);
    const float inv0 = 1.f / s0, inv1 = 1.f / s1;

    // ---- O = P V ----
    float o[4][4];
#pragma unroll
    for (int nf = 0; nf < 4; nf++)
#pragma unroll
        for (int r = 0; r < 4; r++) o[nf][r] = 0.f;

#pragma unroll
    for (int kt = 0; kt < 9; kt++) {
        const int t0 = 2 * kt, t1 = 2 * kt + 1;
        unsigned ah[4], al[4];
        {
            unsigned u0 = __float_as_uint(acc[t0][0]), u1 = __float_as_uint(acc[t0][1]);
            ah[0] = pack_hi(u0, u1);
            al[0] = pack_lo(acc[t0][0], acc[t0][1], u0, u1);
            unsigned u2 = __float_as_uint(acc[t0][2]), u3 = __float_as_uint(acc[t0][3]);
            ah[1] = pack_hi(u2, u3);
            al[1] = pack_lo(acc[t0][2], acc[t0][3], u2, u3);
            unsigned u4 = __float_as_uint(acc[t1][0]), u5 = __float_as_uint(acc[t1][1]);
            ah[2] = pack_hi(u4, u5);
            al[2] = pack_lo(acc[t1][0], acc[t1][1], u4, u5);
            unsigned u6 = __float_as_uint(acc[t1][2]), u7 = __float_as_uint(acc[t1][3]);
            ah[3] = pack_hi(u6, u7);
            al[3] = pack_lo(acc[t1][2], acc[t1][3], u6, u7);
        }
#pragma unroll
        for (int np = 0; np < 2; np++) {
            unsigned vfh[4], vfl[4];
            unsigned off = ((np * 16 + b_ro) * 152 + kt * 16 + b_co) * 2;
            ldsm_x4(vfh, sbase + 23040 * 2 + off);
            ldsm_x4(vfl, sbase + 27904 * 2 + off);
            mma_bf16(o[np * 2],     ah, &vfh[0]);
            mma_bf16(o[np * 2 + 1], ah, &vfh[2]);
            mma_bf16(o[np * 2],     al, &vfh[0]);
            mma_bf16(o[np * 2 + 1], al, &vfh[2]);
            mma_bf16(o[np * 2],     ah, &vfl[0]);
            mma_bf16(o[np * 2 + 1], ah, &vfl[2]);
        }
    }

    float* o0 = g_o + ((size_t)(bw * NTOK + r0g)) * CCH + h * LD;
    float* o1 = g_o + ((size_t)(bw * NTOK + r1g)) * CCH + h * LD;
#pragma unroll
    for (int nf = 0; nf < 4; nf++) {
        int col = nf * 8 + qc * 2;
        float2 w0 = {o[nf][0] * inv0, o[nf][1] * inv0};
        float2 w1 = {o[nf][2] * inv1, o[nf][3] * inv1};
        *(float2*)(o0 + col) = w0;
        *(float2*)(o1 + col) = w1;
    }
}

// ---------------------------------------------------------------------------
extern "C" void kernel_launch(void* const* d_in, const int* in_sizes, int n_in,
                              void* d_out, int out_size)
{
    (void)in_sizes; (void)n_in; (void)out_size;
    const float* x          = (const float*)d_in[0];
    const float* mask       = (const float*)d_in[1];
    const float* qkv_w      = (const float*)d_in[2];
    const float* qkv_b      = (const float*)d_in[3];
    const float* proj_w     = (const float*)d_in[4];
    const float* proj_b     = (const float*)d_in[5];
    const float* bias_table = (const float*)d_in[6];
    float* out = (float*)d_out;

    static const int GEMM_SMEM = 61440;
    static const int ATTN_SMEM = 65536;
    cudaFuncSetAttribute(qkv_mma_kernel,
                         cudaFuncAttributeMaxDynamicSharedMemorySize, GEMM_SMEM);
    cudaFuncSetAttribute(proj_mma_kernel,
                         cudaFuncAttributeMaxDynamicSharedMemorySize, GEMM_SMEM);
    cudaFuncSetAttribute(attn_mma_kernel,
                         cudaFuncAttributeMaxDynamicSharedMemorySize, ATTN_SMEM);

    {
        const int total = NH * NW * NTOK * NTOK;
        bias_gather_kernel<<<(total + 255) / 256, 256>>>(bias_table);
    }
    {
        dim3 grid(THREEC / 64, MROWS / 128);   // (9, 1080)
        qkv_mma_kernel<<<grid, 256, GEMM_SMEM>>>(x, qkv_w, qkv_b);
    }
    attn_mma_kernel<<<B_TOT * NW * NH, 288, ATTN_SMEM>>>(mask);
    {
        dim3 grid(CCH / 64, MROWS / 128);      // (3, 1080)
        proj_mma_kernel<<<grid, 256, GEMM_SMEM>>>(proj_w, proj_b, out);
    }
}